// round 11
// baseline (speedup 1.0000x reference)
#include <cuda_runtime.h>

// QuantumRegression: 1024 x 14-qubit statevector sim, 3 layers (Rot per wire + CNOT ring),
// <Z_w> features, linear head.
//
// R11: NT=1024 (32 warps, 64 regs/thread), 4 passes/layer with 16-amp register tiles:
//   A: bits 13..10 (wires 0..3)  B: 9..6 (4..7)  C: 5..2 (8..11, stagger)  D: 1..0 (12,13, stagger)
// ZYZ with forward-deferred betas: bA,bB(l)->T_A(l+1)[f,t9..6,t0]; bC(l)->T_B(l+1)[f,t5..2];
// bD(l)->T_C(l+1)[m,t1..0]; layer-2 betas dropped at measurement. Frame-tracked CNOT perms;
// measurement folds P^3 into pass D with a 4-amp Walsh butterfly.

#define NW   14
#define DIM  16384
#define NT   1024

typedef unsigned long long u64;

// table offsets (float4 {c,c,-s,s})
#define OFF_TA0 0      // 16  : layer0 entry A, idx f
#define OFF_TB0 16     // 16  : layer0 entry B, idx f
#define OFF_TC0 32     // 16  : layer0 entry C, idx m^u
#define OFF_TD  48     // 12  : entry D per layer, idx L*4 + (m^u)
#define OFF_TA  64     // 2x512 : entry A layers 1,2, idx (f<<5)|(h<<1)|t0
#define OFF_TB  1088   // 2x256 : entry B layers 1,2, idx (f<<4)|g
#define OFF_TC  1600   // 2x64  : entry C layers 1,2, idx (m<<2)|r
#define NTAB    1728

__device__ float2 g_rot[3*NW];          // per-wire (cos g/2, sin g/2)
__device__ float4 g_tab[NTAB];

// ---------------- setup: ZYZ decomposition + deferred-diagonal tables ----------------

struct cpx { float re, im; };
__device__ __forceinline__ cpx cmul(cpx a, cpx b){
    cpx r; r.re = a.re*b.re - a.im*b.im; r.im = a.re*b.im + a.im*b.re; return r;
}

__device__ void rotmat(const float* p, cpx U[2][2]){
    float cx = cosf(0.5f*p[0]), sx = sinf(0.5f*p[0]);
    float cy = cosf(0.5f*p[1]), sy = sinf(0.5f*p[1]);
    float cz = cosf(0.5f*p[2]), sz = sinf(0.5f*p[2]);
    cpx r00 = { cy*cx,  sy*sx};
    cpx r01 = {-sy*cx, -cy*sx};
    cpx r10 = { sy*cx, -cy*sx};
    cpx r11 = { cy*cx, -sy*sx};
    cpx e0 = {cz, -sz}, e1 = {cz, sz};
    U[0][0] = cmul(e0, r00); U[0][1] = cmul(e0, r01);
    U[1][0] = cmul(e1, r10); U[1][1] = cmul(e1, r11);
}

// sum over k<nb of +-a[w0 - k]/2, sign from bit k of `bits` (set -> +)
__device__ __forceinline__ float angsum(const float* a, int w0, int bits, int nb){
    float s = 0.f;
    for (int k = 0; k < nb; k++){
        float h = 0.5f * a[w0 - k];
        s += ((bits >> k) & 1) ? h : -h;
    }
    return s;
}

__global__ void setup_all(const float* __restrict__ vp){
    __shared__ float sb[3*NW], sd[3*NW];
    int t = threadIdx.x;
    if (t < 3*NW){
        cpx U[2][2]; rotmat(vp + t*3, U);
        float na = hypotf(U[0][0].re, U[0][0].im);
        float nc = hypotf(U[1][0].re, U[1][0].im);
        float n  = hypotf(na, nc);
        g_rot[t] = make_float2(na/n, nc/n);
        float beta, delta;
        if (nc > 1e-6f && na > 1e-6f){
            float aa = atan2f(U[0][0].im, U[0][0].re);
            float ac = atan2f(U[1][0].im, U[1][0].re);
            float ad = atan2f(U[1][1].im, U[1][1].re);
            beta = ac - aa; delta = ad - ac;
        } else if (nc <= 1e-6f){                // gamma ~ 0
            delta = 0.f;
            beta = atan2f(U[1][1].im, U[1][1].re) - atan2f(U[0][0].im, U[0][0].re);
        } else {                                // gamma ~ pi
            delta = 0.f;
            beta = atan2f(U[1][0].im, U[1][0].re) - atan2f(-U[0][1].im, -U[0][1].re);
        }
        sb[t] = beta; sd[t] = delta;
    }
    __syncthreads();
    for (int idx = t; idx < NTAB; idx += blockDim.x){
        float ang = 0.f;
        if (idx < OFF_TB0){                                // layer0 entry A
            ang = angsum(sd, 3, idx, 4);
        } else if (idx < OFF_TC0){                         // layer0 entry B
            ang = angsum(sd, 7, idx - OFF_TB0, 4);
        } else if (idx < OFF_TD){                          // layer0 entry C
            ang = angsum(sd, 11, idx - OFF_TC0, 4);
        } else if (idx < OFF_TD + 12){                     // entry D (all layers)
            int r = idx - OFF_TD; int l = r >> 2, m = r & 3;
            ang = angsum(sd, l*NW + 13, m, 2);
        } else if (idx >= OFF_TA && idx < OFF_TB){         // entry A layers 1,2
            int r = idx - OFF_TA; int L = 1 + (r >> 9); r &= 511;
            int f = r >> 5, h = (r >> 1) & 15, t0 = r & 1;
            int sA = (f ^ (f >> 1)) ^ (t0 ? 12 : 0);       // betaA(L-1), wires 0..3
            int sB = (h ^ (h >> 1)) ^ ((f & 1) ? 8 : 0);   // betaB(L-1), wires 4..7
            ang = angsum(sd, L*NW + 3, f, 4)
                + angsum(sb, (L-1)*NW + 3, sA, 4)
                + angsum(sb, (L-1)*NW + 7, sB, 4);
        } else if (idx >= OFF_TB && idx < OFF_TC){         // entry B layers 1,2
            int r = idx - OFF_TB; int L = 1 + (r >> 8); r &= 255;
            int f = r >> 4, g = r & 15;
            int sC = (g ^ (g >> 1)) ^ ((f & 1) ? 8 : 0);   // betaC(L-1), wires 8..11
            ang = angsum(sd, L*NW + 7, f, 4)
                + angsum(sb, (L-1)*NW + 11, sC, 4);
        } else if (idx >= OFF_TC && idx < NTAB){           // entry C layers 1,2
            int r = idx - OFF_TC; int L = 1 + (r >> 6); r &= 63;
            int m = r >> 2, rr = r & 3;
            int r0 = rr & 1, r1 = (rr >> 1) & 1, m0 = m & 1;
            int sD = (r0 ^ r1) | ((r1 ^ m0) << 1);         // betaD(L-1), wires 12,13
            ang = angsum(sd, L*NW + 11, m, 4)
                + angsum(sb, (L-1)*NW + 13, sD, 2);
        } else {
            ang = 0.f;                                     // pad
        }
        float sp, cp; sincosf(ang, &sp, &cp);
        g_tab[idx] = make_float4(cp, cp, -sp, sp);
    }
}

// ---------------- packed f32x2 helpers ----------------

__device__ __forceinline__ u64 pk2(float lo, float hi){
    u64 r; asm("mov.b64 %0, {%1,%2};" : "=l"(r) : "f"(lo), "f"(hi)); return r;
}
__device__ __forceinline__ void upk2(u64 v, float& lo, float& hi){
    asm("mov.b64 {%0,%1}, %2;" : "=f"(lo), "=f"(hi) : "l"(v));
}
__device__ __forceinline__ u64 swp2(u64 v){
    u64 r;
    asm("{ .reg .b32 a,b; mov.b64 {a,b}, %1; mov.b64 %0, {b,a}; }" : "=l"(r) : "l"(v));
    return r;
}
__device__ __forceinline__ u64 f2(u64 a, u64 b, u64 c){
    u64 r; asm("fma.rn.f32x2 %0, %1, %2, %3;" : "=l"(r) : "l"(a), "l"(b), "l"(c)); return r;
}
__device__ __forceinline__ u64 m2(u64 a, u64 b){
    u64 r; asm("mul.rn.f32x2 %0, %1, %2;" : "=l"(r) : "l"(a), "l"(b)); return r;
}

// amp *= phase(q)   q = {c,c,-s,s}
__device__ __forceinline__ u64 dmul(u64 amp, float4 q){
    u64 uu = pk2(q.x, q.y), nn = pk2(q.z, q.w);
    return f2(uu, amp, m2(nn, swp2(amp)));
}

// NB real RY rotations on bits NB-1..0 of a 2^NB-amp tile; bit k <-> wire w0-k.
// u-bit set => logical 0/1 roles swapped => s -> -s.
template<int NB>
__device__ __forceinline__ void rotTile(u64* amp, const float2* rot, int w0, int u){
    #pragma unroll
    for (int k = NB-1; k >= 0; k--){
        float2 cs = rot[w0 - k];
        float s = ((u >> k) & 1) ? -cs.y : cs.y;
        u64 cc = pk2(cs.x, cs.x), ss = pk2(s, s), ns = pk2(-s, -s);
        const int bit = 1 << k;
        #pragma unroll
        for (int p = 0; p < (1 << NB); p++)
            if (!(p & bit)){
                u64 v0 = amp[p], v1 = amp[p | bit];
                amp[p]       = f2(cc, v0, m2(ns, v1));
                amp[p | bit] = f2(cc, v1, m2(ss, v0));
            }
    }
}

// ---------------- CNOT-ring permutation (GF2 linear, constexpr-foldable) ----------------
__host__ __device__ __forceinline__ constexpr int cpfwd(int i){
    int y = i;
    y ^= y >> 1; y ^= y >> 2; y ^= y >> 4; y ^= y >> 8;
    return (y & 0x1FFF) ^ ((((y ^ (i >> 13)) & 1) << 13));
}
__host__ __device__ __forceinline__ constexpr int cpinv(int o){
    int t = o ^ (o >> 1);
    return (t & 0x1FFF) ^ (o & 0x2000) ^ ((o & 1) ? 0x3000 : 0);
}
template<int L>
__host__ __device__ __forceinline__ constexpr int pinvL(int x){
    return (L == 0) ? x : (L == 1) ? cpinv(x) : cpinv(cpinv(x));
}

// ---------------- passes (one 16-amp tile per thread for A,B,C; 4x4-amp for D) --------

// pass A: logical bits 13..10 (wires 0..3), layer L.
template<int L>
__device__ __forceinline__ void passA(float2* psi, const float4* stab, const float2* srot, int t){
    int base = pinvL<L>(t);
    u64 amp[16];
    if (L == 0){
        const float4* tab = stab + OFF_TA0;
        #pragma unroll
        for (int f = 0; f < 16; f++){
            float2 a = psi[base ^ pinvL<L>(f << 10)];
            amp[f] = dmul(pk2(a.x, a.y), tab[f]);
        }
    } else {
        const float4* tab = stab + OFF_TA + (L-1)*512 + ((((t >> 6) & 15) << 1) | (t & 1));
        #pragma unroll
        for (int f = 0; f < 16; f++){
            float2 a = psi[base ^ pinvL<L>(f << 10)];
            amp[f] = dmul(pk2(a.x, a.y), tab[f << 5]);
        }
    }
    rotTile<4>(amp, srot, L*NW + 3, 0);
    #pragma unroll
    for (int f = 0; f < 16; f++){
        float xx, yy; upk2(amp[f], xx, yy);
        psi[base ^ pinvL<L>(f << 10)] = make_float2(xx, yy);
    }
}

// pass B: logical bits 9..6 (wires 4..7), layer L.
template<int L>
__device__ __forceinline__ void passB(float2* psi, const float4* stab, const float2* srot, int t){
    int x = ((t >> 6) << 10) | (t & 63);
    int base = pinvL<L>(x);
    u64 amp[16];
    if (L == 0){
        const float4* tab = stab + OFF_TB0;
        #pragma unroll
        for (int f = 0; f < 16; f++){
            float2 a = psi[base ^ pinvL<L>(f << 6)];
            amp[f] = dmul(pk2(a.x, a.y), tab[f]);
        }
    } else {
        const float4* tab = stab + OFF_TB + (L-1)*256 + ((t >> 2) & 15);
        #pragma unroll
        for (int f = 0; f < 16; f++){
            float2 a = psi[base ^ pinvL<L>(f << 6)];
            amp[f] = dmul(pk2(a.x, a.y), tab[f << 4]);
        }
    }
    rotTile<4>(amp, srot, L*NW + 7, 0);
    #pragma unroll
    for (int f = 0; f < 16; f++){
        float xx, yy; upk2(amp[f], xx, yy);
        psi[base ^ pinvL<L>(f << 6)] = make_float2(xx, yy);
    }
}

// pass C: logical bits 5..2 (wires 8..11), layer L; XOR stagger u = (t>>2)&3.
template<int L>
__device__ __forceinline__ void passC(float2* psi, const float4* stab, const float2* srot, int t){
    const int u = (t >> 2) & 3;
    int x = ((t >> 2) << 6) | (t & 3);
    int base = pinvL<L>(x) ^ pinvL<L>(u << 2);
    u64 amp[16];
    if (L == 0){
        const float4* tab = stab + OFF_TC0;
        #pragma unroll
        for (int m = 0; m < 16; m++){
            float2 a = psi[base ^ pinvL<L>(m << 2)];
            amp[m] = dmul(pk2(a.x, a.y), tab[m ^ u]);
        }
    } else {
        const float4* tab = stab + OFF_TC + (L-1)*64 + (t & 3);
        #pragma unroll
        for (int m = 0; m < 16; m++){
            float2 a = psi[base ^ pinvL<L>(m << 2)];
            amp[m] = dmul(pk2(a.x, a.y), tab[(m ^ u) << 2]);
        }
    }
    rotTile<4>(amp, srot, L*NW + 11, u);
    #pragma unroll
    for (int m = 0; m < 16; m++){
        float xx, yy; upk2(amp[m], xx, yy);
        psi[base ^ pinvL<L>(m << 2)] = make_float2(xx, yy);
    }
}

// pass D: logical bits 1..0 (wires 12,13), layer L; 4 tiles of 4 amps per thread.
// MEAS folds P^3 measurement with a 4-amp Walsh butterfly (signs on wires 0,12,13).
template<int L, bool MEAS>
__device__ __forceinline__ void passD(float2* psi, const float4* stab, const float2* srot,
                                      int t, float* zs){
    const int u = (L == 0) ? ((t >> 2) & 3) : ((t >> 3) & 1);
    const int uoff = pinvL<L>(u);
    const float4* tabD = stab + OFF_TD + L*4;
    #pragma unroll 1
    for (int j = 0; j < 4; j++){
        int y = t + NT*j;                         // 12-bit tile index (logical bits 13..2)
        int base = pinvL<L>(y << 2) ^ uoff;
        u64 amp[4];
        #pragma unroll
        for (int m = 0; m < 4; m++){
            float2 a = psi[base ^ pinvL<L>(m)];
            amp[m] = dmul(pk2(a.x, a.y), tabD[m ^ u]);
        }
        rotTile<2>(amp, srot, L*NW + 13, u);
        if (!MEAS){
            #pragma unroll
            for (int m = 0; m < 4; m++){
                float xx, yy; upk2(amp[m], xx, yy);
                psi[base ^ pinvL<L>(m)] = make_float2(xx, yy);
            }
        } else {
            // logical o = cpfwd((y<<2) ^ u ^ m); cpfwd(m) sign bits: bit0=bit13=m0^m1, bit1=m1
            int obase = cpfwd((y << 2) ^ u);
            float pr[4];
            #pragma unroll
            for (int m = 0; m < 4; m++){
                float xx, yy; upk2(amp[m], xx, yy);
                pr[m] = xx*xx + yy*yy;
            }
            float s01 = pr[0] + pr[1], s23 = pr[2] + pr[3];
            float d01 = pr[0] - pr[1], d23 = pr[2] - pr[3];
            float T  = s01 + s23;
            float A2 = s01 - s23;      // sign pattern (-1)^{m1}     -> wire 12 (o bit 1)
            float A1 = d01 - d23;      // sign pattern (-1)^{m0^m1}  -> wires 13 (bit0), 0 (bit13)
            #pragma unroll
            for (int w = 1; w <= 11; w++){
                unsigned msk = ((unsigned)obase << (18 + w)) & 0x80000000u;
                zs[w] += __uint_as_float(__float_as_uint(T) ^ msk);
            }
            zs[12] += __uint_as_float(__float_as_uint(A2) ^ (((unsigned)obase << 30) & 0x80000000u));
            zs[13] += __uint_as_float(__float_as_uint(A1) ^ (((unsigned)obase << 31) & 0x80000000u));
            zs[0]  += __uint_as_float(__float_as_uint(A1) ^ (((unsigned)obase << 18) & 0x80000000u));
        }
    }
}

// ---------------- main kernel ----------------

__global__ void __launch_bounds__(NT, 1)
qsim_kernel(const float* __restrict__ sr, const float* __restrict__ si,
            const float* __restrict__ hw, const float* __restrict__ hb,
            float* __restrict__ out)
{
    extern __shared__ float2 sm[];
    float2* psi = sm;
    float4* stab = reinterpret_cast<float4*>(sm + DIM);               // NTAB float4
    float2* srot = reinterpret_cast<float2*>(stab + NTAB);            // 42 float2
    const int t = threadIdx.x;
    const int b = blockIdx.x;

    // stage tables into smem
    #pragma unroll 1
    for (int i = t; i < NTAB; i += NT) stab[i] = g_tab[i];
    if (t < 3*NW) srot[t] = g_rot[t];
    __syncthreads();

    // ---- layer 0 pass A fused with global load ----
    {
        const float* srb = sr + (size_t)b * DIM;
        const float* sib = si + (size_t)b * DIM;
        const float4* tab = stab + OFF_TA0;
        u64 amp[16];
        #pragma unroll
        for (int f = 0; f < 16; f++){
            float re = __ldg(srb + (f << 10) + t);
            float im = __ldg(sib + (f << 10) + t);
            amp[f] = dmul(pk2(re, im), tab[f]);
        }
        rotTile<4>(amp, srot, 3, 0);
        #pragma unroll
        for (int f = 0; f < 16; f++){
            float x, y; upk2(amp[f], x, y);
            psi[(f << 10) + t] = make_float2(x, y);
        }
    }
    __syncthreads();
    passB<0>(psi, stab, srot, t);           __syncthreads();
    passC<0>(psi, stab, srot, t);           __syncthreads();
    passD<0,false>(psi, stab, srot, t, 0);  __syncthreads();

    passA<1>(psi, stab, srot, t);           __syncthreads();
    passB<1>(psi, stab, srot, t);           __syncthreads();
    passC<1>(psi, stab, srot, t);           __syncthreads();
    passD<1,false>(psi, stab, srot, t, 0);  __syncthreads();

    passA<2>(psi, stab, srot, t);           __syncthreads();
    passB<2>(psi, stab, srot, t);           __syncthreads();
    passC<2>(psi, stab, srot, t);           __syncthreads();

    // ---- layer 2 pass D + measurement (P^3 folded; layer-2 betas dropped) ----
    float zs[NW];
    #pragma unroll
    for (int w = 0; w < NW; w++) zs[w] = 0.f;
    passD<2,true>(psi, stab, srot, t, zs);

    // warp reduce
    #pragma unroll
    for (int off = 16; off > 0; off >>= 1)
        #pragma unroll
        for (int w = 0; w < NW; w++)
            zs[w] += __shfl_down_sync(0xffffffffu, zs[w], off);
    __syncthreads();                       // all psi reads done; reuse as scratch
    float* red = (float*)psi;
    const int NWARP = NT/32;
    int lane = t & 31, wid = t >> 5;
    if (lane == 0){
        #pragma unroll
        for (int w = 0; w < NW; w++) red[w*NWARP + wid] = zs[w];
    }
    __syncthreads();
    if (t == 0){
        float acc = __ldg(hb);
        #pragma unroll
        for (int w = 0; w < NW; w++){
            float f = 0.f;
            #pragma unroll
            for (int r = 0; r < NWARP; r++) f += red[w*NWARP + r];
            acc += f * __ldg(hw + w);
        }
        out[b] = acc;
    }
}

// ---------------- launch ----------------

extern "C" void kernel_launch(void* const* d_in, const int* in_sizes, int n_in,
                              void* d_out, int out_size)
{
    const float* sr = (const float*)d_in[0];
    const float* si = (const float*)d_in[1];
    const float* vp = (const float*)d_in[2];
    const float* hw = (const float*)d_in[3];
    const float* hb = (const float*)d_in[4];
    float* out = (float*)d_out;

    const int SMEM = DIM*sizeof(float2) + NTAB*sizeof(float4) + 3*NW*sizeof(float2);

    cudaFuncSetAttribute(qsim_kernel, cudaFuncAttributeMaxDynamicSharedMemorySize, SMEM);

    setup_all<<<1, 1024>>>(vp);

    int B = in_sizes[0] / DIM;
    qsim_kernel<<<B, NT, SMEM>>>(sr, si, hw, hb, out);
}